// round 14
// baseline (speedup 1.0000x reference)
#include <cuda_runtime.h>
#include <cuda_bf16.h>
#include <math.h>

#define T_TOKENS 8192
#define HID      1024
#define NE       64
#define TOPK     8
#define INTER    512
#define TK       (T_TOKENS * TOPK)     // 65536 (token, expert) pairs
#define TILE_M   64
#define MAX_TILES (TK / TILE_M + NE)   // 1088

typedef __nv_bfloat16 bf16;

// ----------------------------------------------------------------------------
// Tiny device globals only (~1 MiB): harness memory guard counts lazily
// committed statics, so all large scratch lives in SMEM of the fused kernel.
// ----------------------------------------------------------------------------
__device__ int   g_indices[TK];
__device__ float g_rweight[TK];
__device__ int   g_row_token[TK];      // slot -> token
__device__ float g_slot_w[TK];         // slot -> routing weight
__device__ int   g_counts[NE];
__device__ int   g_fill[NE];
__device__ int   g_offsets[NE + 1];
__device__ int   g_tile_off[NE + 1];   // 64-row tiles
__device__ int   g_total_tiles;

// ----------------------------------------------------------------------------
__global__ void init_kernel() {
    int i = threadIdx.x;
    if (i < NE) { g_counts[i] = 0; g_fill[i] = 0; }
}

__global__ void zero_out_kernel(float* __restrict__ out) {
    size_t i = (size_t)blockIdx.x * blockDim.x + threadIdx.x;
    *(float4*)&out[i * 4] = make_float4(0.f, 0.f, 0.f, 0.f);
}

// ----------------------------------------------------------------------------
// fp32 pair -> bf16 hi-pair u32 + bf16 residual-pair u32
// ----------------------------------------------------------------------------
__device__ __forceinline__ void split_pack(float a, float b,
                                           unsigned& hi, unsigned& lo) {
    __nv_bfloat162 h = __float22bfloat162_rn(make_float2(a, b));
    float2 hf = __bfloat1622float2(h);
    __nv_bfloat162 l = __float22bfloat162_rn(make_float2(a - hf.x, b - hf.y));
    hi = *(unsigned*)&h;
    lo = *(unsigned*)&l;
}

// ----------------------------------------------------------------------------
// Router (fp32, exact): logits -> top8 -> softmax over top8
// ----------------------------------------------------------------------------
__global__ void __launch_bounds__(256) router_kernel(const float* __restrict__ x,
                                                     const float* __restrict__ rw) {
    __shared__ float Xs[16][128];
    __shared__ float RWs[128][64];
    __shared__ float Ls[16][64];

    int tid = threadIdx.x;
    int t0  = blockIdx.x * 16;
    int e   = tid & 63;
    int tg  = tid >> 6;

    float acc0 = 0.f, acc1 = 0.f, acc2 = 0.f, acc3 = 0.f;

    for (int h0 = 0; h0 < HID; h0 += 128) {
        #pragma unroll
        for (int r = 0; r < 2; r++) {
            int f = tid + 256 * r;
            int tok = f >> 5, c4 = f & 31;
            *(float4*)&Xs[tok][c4 * 4] =
                *(const float4*)&x[(size_t)(t0 + tok) * HID + h0 + c4 * 4];
        }
        #pragma unroll
        for (int r = 0; r < 8; r++) {
            int f = tid + 256 * r;
            int hh = f >> 4, e4 = f & 15;
            *(float4*)&RWs[hh][e4 * 4] =
                *(const float4*)&rw[(size_t)(h0 + hh) * NE + e4 * 4];
        }
        __syncthreads();
        #pragma unroll 4
        for (int hh = 0; hh < 128; hh++) {
            float w = RWs[hh][e];
            acc0 += Xs[tg * 4 + 0][hh] * w;
            acc1 += Xs[tg * 4 + 1][hh] * w;
            acc2 += Xs[tg * 4 + 2][hh] * w;
            acc3 += Xs[tg * 4 + 3][hh] * w;
        }
        __syncthreads();
    }
    Ls[tg * 4 + 0][e] = acc0;
    Ls[tg * 4 + 1][e] = acc1;
    Ls[tg * 4 + 2][e] = acc2;
    Ls[tg * 4 + 3][e] = acc3;
    __syncthreads();

    if (tid < 16) {
        int t = tid;
        int   idx[TOPK];
        float val[TOPK];
        #pragma unroll
        for (int k = 0; k < TOPK; k++) {
            float best = -1e30f; int bi = 0;
            for (int ee = 0; ee < NE; ee++) {
                float v = Ls[t][ee];
                if (v > best) { best = v; bi = ee; }
            }
            idx[k] = bi; val[k] = best;
            Ls[t][bi] = -1e30f;
        }
        float m = val[0], s = 0.f, w[TOPK];
        #pragma unroll
        for (int k = 0; k < TOPK; k++) { w[k] = expf(val[k] - m); s += w[k]; }
        float inv = 1.f / s;
        int base = (t0 + t) * TOPK;
        #pragma unroll
        for (int k = 0; k < TOPK; k++) {
            g_indices[base + k] = idx[k];
            g_rweight[base + k] = w[k] * inv;
            atomicAdd(&g_counts[idx[k]], 1);
        }
    }
}

// ----------------------------------------------------------------------------
__global__ void scan_kernel() {
    int off = 0, toff = 0;
    g_offsets[0] = 0; g_tile_off[0] = 0;
    for (int e = 0; e < NE; e++) {
        off  += g_counts[e];               g_offsets[e + 1]  = off;
        toff += (g_counts[e] + 63) >> 6;   g_tile_off[e + 1] = toff;
    }
    g_total_tiles = toff;
}

__global__ void scatter_kernel() {
    int i = blockIdx.x * blockDim.x + threadIdx.x;
    if (i >= TK) return;
    int e    = g_indices[i];
    int pos  = atomicAdd(&g_fill[e], 1);
    int slot = g_offsets[e] + pos;
    g_row_token[slot] = i >> 3;
    g_slot_w[slot]    = g_rweight[i];
}

// ----------------------------------------------------------------------------
__device__ __forceinline__ void mma_bf16(float* c, const unsigned* a, const unsigned* b) {
    asm volatile(
        "mma.sync.aligned.m16n8k16.row.col.f32.bf16.bf16.f32 "
        "{%0,%1,%2,%3}, {%4,%5,%6,%7}, {%8,%9}, {%0,%1,%2,%3};"
        : "+f"(c[0]), "+f"(c[1]), "+f"(c[2]), "+f"(c[3])
        : "r"(a[0]), "r"(a[1]), "r"(a[2]), "r"(a[3]), "r"(b[0]), "r"(b[1]));
}

// dynamic SMEM partition (u32 units)
#define U_BS_HI  0u        // 2 bufs x (256 rows x 20)
#define U_BS_LO  10240u
#define U_ACT_HI 20480u    // 64 rows x 260 (256 k-pairs + pad)
#define U_ACT_LO 37120u
#define U_TOTAL  53760u
#define SMEM_BYTES (U_TOTAL * 4)   // 215040

// ----------------------------------------------------------------------------
// Fused expert kernel: one 64-row slot tile per block, 256 threads (8 warps,
// warp grid 2m x 4n). 3-term bf16-split MMA (C += Ah*Bh + Ah*Bl + Al*Bh).
// A fragments live in REGISTERS (per-lane LDG.64 straight from the gathered
// rows, split in-registers) — no A smem, no A staging sync. B tiles are
// ping-pong double-buffered in SMEM: ONE __syncthreads per 32-k chunk, with
// the next chunk's B load+split+store overlapped under the current MMAs.
// Phase A: 4 passes x (128 gate + 128 up cols), K=1024; SiLU -> act SMEM
//          (bf16 hi/lo k-pairs, row stride 260 = conflict-free).
// Phase B: 8 passes x 128 cols, K=512; A-frags from act SMEM (static);
//          epilogue fused combine via atomicAdd(out[token], w*val).
// ----------------------------------------------------------------------------
__global__ void __launch_bounds__(256) fused_moe_kernel(
    const float* __restrict__ x, const float* __restrict__ wgu,
    const float* __restrict__ wd, float* __restrict__ out) {

    extern __shared__ unsigned sm[];

    int bm = blockIdx.x;
    if (bm >= g_total_tiles) return;
    int e = 0;
    while (e < NE - 1 && g_tile_off[e + 1] <= bm) e++;
    int row_start  = g_offsets[e] + (bm - g_tile_off[e]) * TILE_M;
    int rows_valid = g_offsets[e + 1] - row_start;
    if (rows_valid > TILE_M) rows_valid = TILE_M;

    int tid  = threadIdx.x;
    int lane = tid & 31;
    int wid  = tid >> 5;
    int wm   = (wid >> 2) * 32;    // warp m offset (0/32)
    int wn   = (wid & 3) * 32;     // warp n offset (0..96)
    int gq   = lane >> 2;
    int tq   = lane & 3;

    // --- A fragment row pointers (4 rows per lane, gathered, clamped) ---
    const float* rowp[4];
    #pragma unroll
    for (int j = 0; j < 4; j++) {
        int rj = wm + 16 * (j >> 1) + 8 * (j & 1) + gq;
        int rc = rj < rows_valid ? rj : 0;
        rowp[j] = x + (size_t)g_row_token[row_start + rc] * HID;
    }

    // Phase A B loader: one n-row (0..255; gate<128, up>=128), 32 k per chunk
    int bnA = tid;
    // Phase B loader: one n-row (0..127) x one 16-k half
    int bnB = tid & 127, bkhB = tid >> 7;

    const float* wgu_e = wgu + (size_t)e * HID * 1024;
    const float* wd_e  = wd + (size_t)e * INTER * 1024;

    // register A fragments (current chunk)
    unsigned ah[2][2][4], al[2][2][4];

    // =========================== Phase A ===========================
    for (int nc = 0; nc < 4; nc++) {
        int gcol = (bnA < 128) ? (nc * 128 + bnA) : (512 + nc * 128 + (bnA - 128));
        const float* wpA = wgu_e + gcol;

        float accg[2][4][4], accu[2][4][4];
        #pragma unroll
        for (int mi = 0; mi < 2; mi++)
            #pragma unroll
            for (int ni = 0; ni < 4; ni++)
                #pragma unroll
                for (int q = 0; q < 4; q++) { accg[mi][ni][q] = 0.f; accu[mi][ni][q] = 0.f; }

        auto loadA = [&](int kbase) {
            #pragma unroll
            for (int mi = 0; mi < 2; mi++) {
                #pragma unroll
                for (int ks = 0; ks < 2; ks++) {
                    const float* p0 = rowp[2 * mi]     + kbase + 16 * ks + 2 * tq;
                    const float* p1 = rowp[2 * mi + 1] + kbase + 16 * ks + 2 * tq;
                    float2 v0 = *(const float2*)p0;
                    float2 v1 = *(const float2*)p1;
                    float2 v2 = *(const float2*)(p0 + 8);
                    float2 v3 = *(const float2*)(p1 + 8);
                    split_pack(v0.x, v0.y, ah[mi][ks][0], al[mi][ks][0]);
                    split_pack(v1.x, v1.y, ah[mi][ks][1], al[mi][ks][1]);
                    split_pack(v2.x, v2.y, ah[mi][ks][2], al[mi][ks][2]);
                    split_pack(v3.x, v3.y, ah[mi][ks][3], al[mi][ks][3]);
                }
            }
        };
        auto stageB_A = [&](int buf, int kbase) {
            #pragma unroll
            for (int half = 0; half < 2; half++) {
                float v[16];
                const float* bp = wpA + (size_t)(kbase + half * 16) * 1024;
                #pragma unroll
                for (int kk = 0; kk < 16; kk++) v[kk] = bp[(size_t)kk * 1024];
                unsigned h[8], l[8];
                #pragma unroll
                for (int p = 0; p < 8; p++)
                    split_pack(v[2 * p], v[2 * p + 1], h[p], l[p]);
                unsigned o = (unsigned)buf * 5120u + (unsigned)bnA * 20u + half * 8u;
                *(uint4*)&sm[U_BS_HI + o]      = *(uint4*)&h[0];
                *(uint4*)&sm[U_BS_HI + o + 4u] = *(uint4*)&h[4];
                *(uint4*)&sm[U_BS_LO + o]      = *(uint4*)&l[0];
                *(uint4*)&sm[U_BS_LO + o + 4u] = *(uint4*)&l[4];
            }
        };
        auto mmaA = [&](int buf) {
            #pragma unroll
            for (int ks = 0; ks < 2; ks++) {
                #pragma unroll
                for (int ni = 0; ni < 4; ni++) {
                    unsigned rg = (unsigned)buf * 5120u
                                + (unsigned)(wn + ni * 8 + gq) * 20u + ks * 8u;
                    unsigned ru = rg + 2560u;   // up rows = +128*20
                    unsigned Bgh[2] = { sm[U_BS_HI + rg + tq], sm[U_BS_HI + rg + tq + 4] };
                    unsigned Bgl[2] = { sm[U_BS_LO + rg + tq], sm[U_BS_LO + rg + tq + 4] };
                    unsigned Buh[2] = { sm[U_BS_HI + ru + tq], sm[U_BS_HI + ru + tq + 4] };
                    unsigned Bul[2] = { sm[U_BS_LO + ru + tq], sm[U_BS_LO + ru + tq + 4] };
                    #pragma unroll
                    for (int mi = 0; mi < 2; mi++) {
                        mma_bf16(accg[mi][ni], ah[mi][ks], Bgh);
                        mma_bf16(accg[mi][ni], ah[mi][ks], Bgl);
                        mma_bf16(accg[mi][ni], al[mi][ks], Bgh);
                        mma_bf16(accu[mi][ni], ah[mi][ks], Buh);
                        mma_bf16(accu[mi][ni], ah[mi][ks], Bul);
                        mma_bf16(accu[mi][ni], al[mi][ks], Buh);
                    }
                }
            }
        };

        loadA(0);
        stageB_A(0, 0);
        __syncthreads();
        int cur = 0;
        for (int k0 = 0; k0 < HID; k0 += 32) {
            bool more = (k0 + 32 < HID);
            mmaA(cur);
            if (more) {
                loadA(k0 + 32);            // overwrites frags AFTER mma issue
                stageB_A(cur ^ 1, k0 + 32);
            }
            __syncthreads();
            cur ^= 1;
        }

        // SiLU epilogue -> act SMEM (bf16 hi/lo k-pairs)
        #pragma unroll
        for (int mi = 0; mi < 2; mi++) {
            int r0 = wm + mi * 16 + gq, r1 = r0 + 8;
            #pragma unroll
            for (int ni = 0; ni < 4; ni++) {
                int cidx = nc * 64 + (wn >> 1) + ni * 4 + tq;
                float gA = accg[mi][ni][0], gB = accg[mi][ni][1];
                float p0 = gA / (1.f + expf(-gA)) * accu[mi][ni][0];
                float p1 = gB / (1.f + expf(-gB)) * accu[mi][ni][1];
                unsigned h, l;
                split_pack(p0, p1, h, l);
                sm[U_ACT_HI + r0 * 260 + cidx] = h;
                sm[U_ACT_LO + r0 * 260 + cidx] = l;
                gA = accg[mi][ni][2]; gB = accg[mi][ni][3];
                p0 = gA / (1.f + expf(-gA)) * accu[mi][ni][2];
                p1 = gB / (1.f + expf(-gB)) * accu[mi][ni][3];
                split_pack(p0, p1, h, l);
                sm[U_ACT_HI + r1 * 260 + cidx] = h;
                sm[U_ACT_LO + r1 * 260 + cidx] = l;
            }
        }
    }
    __syncthreads();   // act complete before Phase B reads

    // =========================== Phase B ===========================
    for (int nc2 = 0; nc2 < 8; nc2++) {
        int n0 = nc2 * 128;
        const float* wpB = wd_e + n0 + bnB;

        float acc[2][4][4];
        #pragma unroll
        for (int mi = 0; mi < 2; mi++)
            #pragma unroll
            for (int ni = 0; ni < 4; ni++)
                #pragma unroll
                for (int q = 0; q < 4; q++) acc[mi][ni][q] = 0.f;

        auto stageB_B = [&](int buf, int kbase) {
            float v[16];
            const float* bp = wpB + (size_t)(kbase + bkhB * 16) * 1024;
            #pragma unroll
            for (int kk = 0; kk < 16; kk++) v[kk] = bp[(size_t)kk * 1024];
            unsigned h[8], l[8];
            #pragma unroll
            for (int p = 0; p < 8; p++)
                split_pack(v[2 * p], v[2 * p + 1], h[p], l[p]);
            unsigned o = (unsigned)buf * 5120u + (unsigned)bnB * 20u + (unsigned)bkhB * 8u;
            *(uint4*)&sm[U_BS_HI + o]      = *(uint4*)&h[0];
            *(uint4*)&sm[U_BS_HI + o + 4u] = *(uint4*)&h[4];
            *(uint4*)&sm[U_BS_LO + o]      = *(uint4*)&l[0];
            *(uint4*)&sm[U_BS_LO + o + 4u] = *(uint4*)&l[4];
        };
        auto mmaB = [&](int buf, int k0) {
            #pragma unroll
            for (int ks = 0; ks < 2; ks++) {
                unsigned Ah[2][4], Al[2][4];
                #pragma unroll
                for (int mi = 0; mi < 2; mi++) {
                    unsigned ab = (unsigned)(wm + mi * 16 + gq) * 260u
                                + (unsigned)(k0 >> 1) + ks * 8u;
                    Ah[mi][0] = sm[U_ACT_HI + ab + tq];
                    Ah[mi][1] = sm[U_ACT_HI + ab + 2080 + tq];
                    Ah[mi][2] = sm[U_ACT_HI + ab + tq + 4];
                    Ah[mi][3] = sm[U_ACT_HI + ab + 2080 + tq + 4];
                    Al[mi][0] = sm[U_ACT_LO + ab + tq];
                    Al[mi][1] = sm[U_ACT_LO + ab + 2080 + tq];
                    Al[mi][2] = sm[U_ACT_LO + ab + tq + 4];
                    Al[mi][3] = sm[U_ACT_LO + ab + 2080 + tq + 4];
                }
                #pragma unroll
                for (int ni = 0; ni < 4; ni++) {
                    unsigned rb = (unsigned)buf * 5120u
                                + (unsigned)(wn + ni * 8 + gq) * 20u + ks * 8u;
                    unsigned Bh[2] = { sm[U_BS_HI + rb + tq], sm[U_BS_HI + rb + tq + 4] };
                    unsigned Bl[2] = { sm[U_BS_LO + rb + tq], sm[U_BS_LO + rb + tq + 4] };
                    #pragma unroll
                    for (int mi = 0; mi < 2; mi++) {
                        mma_bf16(acc[mi][ni], Ah[mi], Bh);
                        mma_bf16(acc[mi][ni], Ah[mi], Bl);
                        mma_bf16(acc[mi][ni], Al[mi], Bh);
                    }
                }
            }
        };

        stageB_B(0, 0);
        __syncthreads();
        int cur = 0;
        for (int k0 = 0; k0 < INTER; k0 += 32) {
            bool more = (k0 + 32 < INTER);
            mmaB(cur, k0);
            if (more) stageB_B(cur ^ 1, k0 + 32);
            __syncthreads();
            cur ^= 1;
        }

        // fused combine: out[token] += w_slot * val
        #pragma unroll
        for (int mi = 0; mi < 2; mi++) {
            int r0 = wm + mi * 16 + gq, r1 = r0 + 8;
            bool v0 = r0 < rows_valid, v1 = r1 < rows_valid;
            int   t0v = 0, t1v = 0;
            float w0 = 0.f, w1 = 0.f;
            if (v0) { t0v = g_row_token[row_start + r0]; w0 = g_slot_w[row_start + r0]; }
            if (v1) { t1v = g_row_token[row_start + r1]; w1 = g_slot_w[row_start + r1]; }
            #pragma unroll
            for (int ni = 0; ni < 4; ni++) {
                int col = n0 + wn + ni * 8 + tq * 2;
                if (v0) {
                    float* o = &out[(size_t)t0v * 1024 + col];
                    atomicAdd(o,     w0 * acc[mi][ni][0]);
                    atomicAdd(o + 1, w0 * acc[mi][ni][1]);
                }
                if (v1) {
                    float* o = &out[(size_t)t1v * 1024 + col];
                    atomicAdd(o,     w1 * acc[mi][ni][2]);
                    atomicAdd(o + 1, w1 * acc[mi][ni][3]);
                }
            }
        }
    }
}

// ----------------------------------------------------------------------------
extern "C" void kernel_launch(void* const* d_in, const int* in_sizes, int n_in,
                              void* d_out, int out_size) {
    const float* x   = (const float*)d_in[0];   // [8192, 1024]
    const float* rw  = (const float*)d_in[1];   // [1024, 64]
    const float* wgu = (const float*)d_in[2];   // [64, 1024, 1024]
    const float* wd  = (const float*)d_in[3];   // [64, 512, 1024]
    float* out = (float*)d_out;                 // [8192, 1024]

    static bool attr_set = false;
    if (!attr_set) {
        cudaFuncSetAttribute(fused_moe_kernel,
                             cudaFuncAttributeMaxDynamicSharedMemorySize,
                             SMEM_BYTES);
        attr_set = true;
    }

    init_kernel<<<1, 64>>>();
    zero_out_kernel<<<(T_TOKENS * HID / 4) / 256, 256>>>(out);
    router_kernel<<<T_TOKENS / 16, 256>>>(x, rw);
    scan_kernel<<<1, 1>>>();
    scatter_kernel<<<TK / 256, 256>>>();
    fused_moe_kernel<<<MAX_TILES, 256, SMEM_BYTES>>>(x, wgu, wd, out);
}

// round 15
// speedup vs baseline: 1.2670x; 1.2670x over previous
#include <cuda_runtime.h>
#include <cuda_bf16.h>
#include <math.h>

#define T_TOKENS 8192
#define HID      1024
#define NE       64
#define TOPK     8
#define INTER    512
#define TK       (T_TOKENS * TOPK)     // 65536 (token, expert) pairs
#define TILE_M   64
#define MAX_TILES (TK / TILE_M + NE)   // 1088

typedef __nv_bfloat16 bf16;

// ----------------------------------------------------------------------------
// Tiny device globals only (~1 MiB): harness memory guard counts lazily
// committed statics, so all large scratch lives in SMEM of the fused kernel.
// ----------------------------------------------------------------------------
__device__ int   g_indices[TK];
__device__ float g_rweight[TK];
__device__ int   g_row_token[TK];      // slot -> token
__device__ float g_slot_w[TK];         // slot -> routing weight
__device__ int   g_counts[NE];
__device__ int   g_fill[NE];
__device__ int   g_offsets[NE + 1];
__device__ int   g_tile_off[NE + 1];   // 64-row tiles
__device__ int   g_total_tiles;

// ----------------------------------------------------------------------------
__global__ void init_kernel() {
    int i = threadIdx.x;
    if (i < NE) { g_counts[i] = 0; g_fill[i] = 0; }
}

__global__ void zero_out_kernel(float* __restrict__ out) {
    size_t i = (size_t)blockIdx.x * blockDim.x + threadIdx.x;
    *(float4*)&out[i * 4] = make_float4(0.f, 0.f, 0.f, 0.f);
}

// ----------------------------------------------------------------------------
// fp32 pair -> bf16 hi-pair u32 + bf16 residual-pair u32
// ----------------------------------------------------------------------------
__device__ __forceinline__ void split_pack(float a, float b,
                                           unsigned& hi, unsigned& lo) {
    __nv_bfloat162 h = __float22bfloat162_rn(make_float2(a, b));
    float2 hf = __bfloat1622float2(h);
    __nv_bfloat162 l = __float22bfloat162_rn(make_float2(a - hf.x, b - hf.y));
    hi = *(unsigned*)&h;
    lo = *(unsigned*)&l;
}

// ----------------------------------------------------------------------------
// Router (fp32, exact): logits -> top8 -> softmax over top8
// ----------------------------------------------------------------------------
__global__ void __launch_bounds__(256) router_kernel(const float* __restrict__ x,
                                                     const float* __restrict__ rw) {
    __shared__ float Xs[16][128];
    __shared__ float RWs[128][64];
    __shared__ float Ls[16][64];

    int tid = threadIdx.x;
    int t0  = blockIdx.x * 16;
    int e   = tid & 63;
    int tg  = tid >> 6;

    float acc0 = 0.f, acc1 = 0.f, acc2 = 0.f, acc3 = 0.f;

    for (int h0 = 0; h0 < HID; h0 += 128) {
        #pragma unroll
        for (int r = 0; r < 2; r++) {
            int f = tid + 256 * r;
            int tok = f >> 5, c4 = f & 31;
            *(float4*)&Xs[tok][c4 * 4] =
                *(const float4*)&x[(size_t)(t0 + tok) * HID + h0 + c4 * 4];
        }
        #pragma unroll
        for (int r = 0; r < 8; r++) {
            int f = tid + 256 * r;
            int hh = f >> 4, e4 = f & 15;
            *(float4*)&RWs[hh][e4 * 4] =
                *(const float4*)&rw[(size_t)(h0 + hh) * NE + e4 * 4];
        }
        __syncthreads();
        #pragma unroll 4
        for (int hh = 0; hh < 128; hh++) {
            float w = RWs[hh][e];
            acc0 += Xs[tg * 4 + 0][hh] * w;
            acc1 += Xs[tg * 4 + 1][hh] * w;
            acc2 += Xs[tg * 4 + 2][hh] * w;
            acc3 += Xs[tg * 4 + 3][hh] * w;
        }
        __syncthreads();
    }
    Ls[tg * 4 + 0][e] = acc0;
    Ls[tg * 4 + 1][e] = acc1;
    Ls[tg * 4 + 2][e] = acc2;
    Ls[tg * 4 + 3][e] = acc3;
    __syncthreads();

    if (tid < 16) {
        int t = tid;
        int   idx[TOPK];
        float val[TOPK];
        #pragma unroll
        for (int k = 0; k < TOPK; k++) {
            float best = -1e30f; int bi = 0;
            for (int ee = 0; ee < NE; ee++) {
                float v = Ls[t][ee];
                if (v > best) { best = v; bi = ee; }
            }
            idx[k] = bi; val[k] = best;
            Ls[t][bi] = -1e30f;
        }
        float m = val[0], s = 0.f, w[TOPK];
        #pragma unroll
        for (int k = 0; k < TOPK; k++) { w[k] = expf(val[k] - m); s += w[k]; }
        float inv = 1.f / s;
        int base = (t0 + t) * TOPK;
        #pragma unroll
        for (int k = 0; k < TOPK; k++) {
            g_indices[base + k] = idx[k];
            g_rweight[base + k] = w[k] * inv;
            atomicAdd(&g_counts[idx[k]], 1);
        }
    }
}

// ----------------------------------------------------------------------------
__global__ void scan_kernel() {
    int off = 0, toff = 0;
    g_offsets[0] = 0; g_tile_off[0] = 0;
    for (int e = 0; e < NE; e++) {
        off  += g_counts[e];               g_offsets[e + 1]  = off;
        toff += (g_counts[e] + 63) >> 6;   g_tile_off[e + 1] = toff;
    }
    g_total_tiles = toff;
}

__global__ void scatter_kernel() {
    int i = blockIdx.x * blockDim.x + threadIdx.x;
    if (i >= TK) return;
    int e    = g_indices[i];
    int pos  = atomicAdd(&g_fill[e], 1);
    int slot = g_offsets[e] + pos;
    g_row_token[slot] = i >> 3;
    g_slot_w[slot]    = g_rweight[i];
}

// ----------------------------------------------------------------------------
__device__ __forceinline__ void mma_bf16(float* c, const unsigned* a, const unsigned* b) {
    asm volatile(
        "mma.sync.aligned.m16n8k16.row.col.f32.bf16.bf16.f32 "
        "{%0,%1,%2,%3}, {%4,%5,%6,%7}, {%8,%9}, {%0,%1,%2,%3};"
        : "+f"(c[0]), "+f"(c[1]), "+f"(c[2]), "+f"(c[3])
        : "r"(a[0]), "r"(a[1]), "r"(a[2]), "r"(a[3]), "r"(b[0]), "r"(b[1]));
}

// dynamic SMEM partition (u32 units). A: 2 bufs x (64 rows x 20) stride 20.
// B: 2 bufs x (256 rows x 18) stride 18 (odd-ish stride => conflict-free
// scalar fragment reads; uint2 stores keep 8B alignment). act: 64 x 260.
#define U_AS_HI  0u        // 2 x 1280
#define U_AS_LO  2560u
#define U_BS_HI  5120u     // 2 x 4608
#define U_BS_LO  14336u
#define U_ACT_HI 23552u    // 16640
#define U_ACT_LO 40192u
#define U_TOTAL  56832u
#define SMEM_BYTES (U_TOTAL * 4)   // 227328

// ----------------------------------------------------------------------------
// Fused expert kernel: one 64-row slot tile per block, 256 threads (8 warps,
// warp grid 2m x 4n, warp tile 32x32). 3-term bf16-split MMA
// (C += Ah*Bh + Ah*Bl + Al*Bh). IDENTICAL numerics/structure to the 2623us
// kernel, with ONE change: A and B tiles are ping-pong double-buffered and
// each 32-k chunk runs prefetch(LDG)->MMA->split+store->ONE sync, hiding the
// staging work and global latency under the tensor pipe.
// ----------------------------------------------------------------------------
__global__ void __launch_bounds__(256) fused_moe_kernel(
    const float* __restrict__ x, const float* __restrict__ wgu,
    const float* __restrict__ wd, float* __restrict__ out) {

    extern __shared__ unsigned sm[];

    int bm = blockIdx.x;
    if (bm >= g_total_tiles) return;
    int e = 0;
    while (e < NE - 1 && g_tile_off[e + 1] <= bm) e++;
    int row_start  = g_offsets[e] + (bm - g_tile_off[e]) * TILE_M;
    int rows_valid = g_offsets[e + 1] - row_start;
    if (rows_valid > TILE_M) rows_valid = TILE_M;

    int tid  = threadIdx.x;
    int lane = tid & 31;
    int wid  = tid >> 5;
    int wm   = (wid >> 2) * 32;    // warp m offset (0/32)
    int wn   = (wid & 3) * 32;     // warp n offset (0..96)
    int gq   = lane >> 2;
    int tq   = lane & 3;

    // A loader: row = tid>>2 (0..63), 8-float granule = tid&3
    int arow = tid >> 2, g4 = tid & 3;
    int ar   = arow < rows_valid ? arow : 0;
    const float* afp = x + (size_t)g_row_token[row_start + ar] * HID + g4 * 8;
    int as_w = arow * 20 + g4 * 4;

    // Phase A B loader: one n-row (0..255; gate<128, up>=128) per thread
    int bnA = tid;
    // Phase B loader: one n-row (0..127) x one 16-k half
    int bnB = tid & 127, bkhB = tid >> 7;

    const float* wgu_e = wgu + (size_t)e * HID * 1024;
    const float* wd_e  = wd + (size_t)e * INTER * 1024;

    // =========================== Phase A ===========================
    for (int nc = 0; nc < 4; nc++) {
        int gcol = (bnA < 128) ? (nc * 128 + bnA) : (512 + nc * 128 + (bnA - 128));
        const float* wpA = wgu_e + gcol;

        float accg[2][4][4], accu[2][4][4];
        #pragma unroll
        for (int mi = 0; mi < 2; mi++)
            #pragma unroll
            for (int ni = 0; ni < 4; ni++)
                #pragma unroll
                for (int q = 0; q < 4; q++) { accg[mi][ni][q] = 0.f; accu[mi][ni][q] = 0.f; }

        float4 a0v, a1v;
        float  bv[32];   // 32 weights (both 16-k halves of this thread's column)

        auto loadA = [&](int kbase) {
            a0v = *(const float4*)(afp + kbase);
            a1v = *(const float4*)(afp + kbase + 4);
            #pragma unroll
            for (int half = 0; half < 2; half++) {
                const float* bp = wpA + (size_t)(kbase + half * 16) * 1024;
                #pragma unroll
                for (int kk = 0; kk < 16; kk++)
                    bv[half * 16 + kk] = bp[(size_t)kk * 1024];
            }
        };
        auto stageA = [&](int buf) {
            uint4 ha, la;
            split_pack(a0v.x, a0v.y, ha.x, la.x);
            split_pack(a0v.z, a0v.w, ha.y, la.y);
            split_pack(a1v.x, a1v.y, ha.z, la.z);
            split_pack(a1v.z, a1v.w, ha.w, la.w);
            *(uint4*)&sm[U_AS_HI + buf * 1280 + as_w] = ha;
            *(uint4*)&sm[U_AS_LO + buf * 1280 + as_w] = la;
            #pragma unroll
            for (int half = 0; half < 2; half++) {
                unsigned h[8], l[8];
                #pragma unroll
                for (int p = 0; p < 8; p++)
                    split_pack(bv[half * 16 + 2 * p], bv[half * 16 + 2 * p + 1],
                               h[p], l[p]);
                unsigned o = (unsigned)buf * 4608u + (unsigned)bnA * 18u + half * 8u;
                #pragma unroll
                for (int q = 0; q < 4; q++) {
                    *(uint2*)&sm[U_BS_HI + o + 2u * q] = *(uint2*)&h[2 * q];
                    *(uint2*)&sm[U_BS_LO + o + 2u * q] = *(uint2*)&l[2 * q];
                }
            }
        };
        auto mmaA = [&](int buf) {
            unsigned ab = (unsigned)buf * 1280u;
            unsigned bb = (unsigned)buf * 4608u;
            #pragma unroll
            for (int ks = 0; ks < 2; ks++) {
                unsigned Ah[2][4], Al[2][4];
                #pragma unroll
                for (int mi = 0; mi < 2; mi++) {
                    unsigned ra = ab + (unsigned)(wm + mi * 16 + gq) * 20u + ks * 8u;
                    Ah[mi][0] = sm[U_AS_HI + ra + tq];
                    Ah[mi][1] = sm[U_AS_HI + ra + 160 + tq];
                    Ah[mi][2] = sm[U_AS_HI + ra + tq + 4];
                    Ah[mi][3] = sm[U_AS_HI + ra + 160 + tq + 4];
                    Al[mi][0] = sm[U_AS_LO + ra + tq];
                    Al[mi][1] = sm[U_AS_LO + ra + 160 + tq];
                    Al[mi][2] = sm[U_AS_LO + ra + tq + 4];
                    Al[mi][3] = sm[U_AS_LO + ra + 160 + tq + 4];
                }
                #pragma unroll
                for (int ni = 0; ni < 4; ni++) {
                    unsigned rg = bb + (unsigned)(wn + ni * 8 + gq) * 18u + ks * 8u;
                    unsigned ru = rg + 2304u;   // +128 rows * 18
                    unsigned Bgh[2] = { sm[U_BS_HI + rg + tq], sm[U_BS_HI + rg + tq + 4] };
                    unsigned Bgl[2] = { sm[U_BS_LO + rg + tq], sm[U_BS_LO + rg + tq + 4] };
                    unsigned Buh[2] = { sm[U_BS_HI + ru + tq], sm[U_BS_HI + ru + tq + 4] };
                    unsigned Bul[2] = { sm[U_BS_LO + ru + tq], sm[U_BS_LO + ru + tq + 4] };
                    #pragma unroll
                    for (int mi = 0; mi < 2; mi++) {
                        mma_bf16(accg[mi][ni], Ah[mi], Bgh);
                        mma_bf16(accg[mi][ni], Ah[mi], Bgl);
                        mma_bf16(accg[mi][ni], Al[mi], Bgh);
                        mma_bf16(accu[mi][ni], Ah[mi], Buh);
                        mma_bf16(accu[mi][ni], Ah[mi], Bul);
                        mma_bf16(accu[mi][ni], Al[mi], Buh);
                    }
                }
            }
        };

        loadA(0);
        stageA(0);
        __syncthreads();
        int cur = 0;
        for (int k0 = 0; k0 < HID; k0 += 32) {
            bool more = (k0 + 32 < HID);
            if (more) loadA(k0 + 32);   // LDG latency hides under MMAs
            mmaA(cur);
            if (more) stageA(cur ^ 1);  // split + STS to the other buffer
            __syncthreads();
            cur ^= 1;
        }

        // SiLU epilogue -> act SMEM (bf16 hi/lo k-pairs, stride 260)
        #pragma unroll
        for (int mi = 0; mi < 2; mi++) {
            int r0 = wm + mi * 16 + gq, r1 = r0 + 8;
            #pragma unroll
            for (int ni = 0; ni < 4; ni++) {
                int cidx = nc * 64 + (wn >> 1) + ni * 4 + tq;
                float gA = accg[mi][ni][0], gB = accg[mi][ni][1];
                float p0 = gA / (1.f + expf(-gA)) * accu[mi][ni][0];
                float p1 = gB / (1.f + expf(-gB)) * accu[mi][ni][1];
                unsigned h, l;
                split_pack(p0, p1, h, l);
                sm[U_ACT_HI + r0 * 260 + cidx] = h;
                sm[U_ACT_LO + r0 * 260 + cidx] = l;
                gA = accg[mi][ni][2]; gB = accg[mi][ni][3];
                p0 = gA / (1.f + expf(-gA)) * accu[mi][ni][2];
                p1 = gB / (1.f + expf(-gB)) * accu[mi][ni][3];
                split_pack(p0, p1, h, l);
                sm[U_ACT_HI + r1 * 260 + cidx] = h;
                sm[U_ACT_LO + r1 * 260 + cidx] = l;
            }
        }
    }
    __syncthreads();   // act complete before Phase B reads

    // =========================== Phase B ===========================
    for (int nc2 = 0; nc2 < 8; nc2++) {
        int n0 = nc2 * 128;
        const float* wpB = wd_e + n0 + bnB;

        float acc[2][4][4];
        #pragma unroll
        for (int mi = 0; mi < 2; mi++)
            #pragma unroll
            for (int ni = 0; ni < 4; ni++)
                #pragma unroll
                for (int q = 0; q < 4; q++) acc[mi][ni][q] = 0.f;

        float bv[16];
        auto loadB = [&](int kbase) {
            const float* bp = wpB + (size_t)(kbase + bkhB * 16) * 1024;
            #pragma unroll
            for (int kk = 0; kk < 16; kk++) bv[kk] = bp[(size_t)kk * 1024];
        };
        auto stageB = [&](int buf) {
            unsigned h[8], l[8];
            #pragma unroll
            for (int p = 0; p < 8; p++)
                split_pack(bv[2 * p], bv[2 * p + 1], h[p], l[p]);
            unsigned o = (unsigned)buf * 4608u + (unsigned)bnB * 18u
                       + (unsigned)bkhB * 8u;
            #pragma unroll
            for (int q = 0; q < 4; q++) {
                *(uint2*)&sm[U_BS_HI + o + 2u * q] = *(uint2*)&h[2 * q];
                *(uint2*)&sm[U_BS_LO + o + 2u * q] = *(uint2*)&l[2 * q];
            }
        };
        auto mmaB = [&](int buf, int k0) {
            unsigned bb = (unsigned)buf * 4608u;
            #pragma unroll
            for (int ks = 0; ks < 2; ks++) {
                unsigned Ah[2][4], Al[2][4];
                #pragma unroll
                for (int mi = 0; mi < 2; mi++) {
                    unsigned ab = (unsigned)(wm + mi * 16 + gq) * 260u
                                + (unsigned)(k0 >> 1) + ks * 8u;
                    Ah[mi][0] = sm[U_ACT_HI + ab + tq];
                    Ah[mi][1] = sm[U_ACT_HI + ab + 2080 + tq];
                    Ah[mi][2] = sm[U_ACT_HI + ab + tq + 4];
                    Ah[mi][3] = sm[U_ACT_HI + ab + 2080 + tq + 4];
                    Al[mi][0] = sm[U_ACT_LO + ab + tq];
                    Al[mi][1] = sm[U_ACT_LO + ab + 2080 + tq];
                    Al[mi][2] = sm[U_ACT_LO + ab + tq + 4];
                    Al[mi][3] = sm[U_ACT_LO + ab + 2080 + tq + 4];
                }
                #pragma unroll
                for (int ni = 0; ni < 4; ni++) {
                    unsigned rb = bb + (unsigned)(wn + ni * 8 + gq) * 18u + ks * 8u;
                    unsigned Bh[2] = { sm[U_BS_HI + rb + tq], sm[U_BS_HI + rb + tq + 4] };
                    unsigned Bl[2] = { sm[U_BS_LO + rb + tq], sm[U_BS_LO + rb + tq + 4] };
                    #pragma unroll
                    for (int mi = 0; mi < 2; mi++) {
                        mma_bf16(acc[mi][ni], Ah[mi], Bh);
                        mma_bf16(acc[mi][ni], Ah[mi], Bl);
                        mma_bf16(acc[mi][ni], Al[mi], Bh);
                    }
                }
            }
        };

        loadB(0);
        stageB(0);
        __syncthreads();
        int cur = 0;
        for (int k0 = 0; k0 < INTER; k0 += 32) {
            bool more = (k0 + 32 < INTER);
            if (more) loadB(k0 + 32);
            mmaB(cur, k0);
            if (more) stageB(cur ^ 1);
            __syncthreads();
            cur ^= 1;
        }

        // fused combine: out[token] += w_slot * val
        #pragma unroll
        for (int mi = 0; mi < 2; mi++) {
            int r0 = wm + mi * 16 + gq, r1 = r0 + 8;
            bool v0 = r0 < rows_valid, v1 = r1 < rows_valid;
            int   t0v = 0, t1v = 0;
            float w0 = 0.f, w1 = 0.f;
            if (v0) { t0v = g_row_token[row_start + r0]; w0 = g_slot_w[row_start + r0]; }
            if (v1) { t1v = g_row_token[row_start + r1]; w1 = g_slot_w[row_start + r1]; }
            #pragma unroll
            for (int ni = 0; ni < 4; ni++) {
                int col = n0 + wn + ni * 8 + tq * 2;
                if (v0) {
                    float* o = &out[(size_t)t0v * 1024 + col];
                    atomicAdd(o,     w0 * acc[mi][ni][0]);
                    atomicAdd(o + 1, w0 * acc[mi][ni][1]);
                }
                if (v1) {
                    float* o = &out[(size_t)t1v * 1024 + col];
                    atomicAdd(o,     w1 * acc[mi][ni][2]);
                    atomicAdd(o + 1, w1 * acc[mi][ni][3]);
                }
            }
        }
    }
}

// ----------------------------------------------------------------------------
extern "C" void kernel_launch(void* const* d_in, const int* in_sizes, int n_in,
                              void* d_out, int out_size) {
    const float* x   = (const float*)d_in[0];   // [8192, 1024]
    const float* rw  = (const float*)d_in[1];   // [1024, 64]
    const float* wgu = (const float*)d_in[2];   // [64, 1024, 1024]
    const float* wd  = (const float*)d_in[3];   // [64, 512, 1024]
    float* out = (float*)d_out;                 // [8192, 1024]

    static bool attr_set = false;
    if (!attr_set) {
        cudaFuncSetAttribute(fused_moe_kernel,
                             cudaFuncAttributeMaxDynamicSharedMemorySize,
                             SMEM_BYTES);
        attr_set = true;
    }

    init_kernel<<<1, 64>>>();
    zero_out_kernel<<<(T_TOKENS * HID / 4) / 256, 256>>>(out);
    router_kernel<<<T_TOKENS / 16, 256>>>(x, rw);
    scan_kernel<<<1, 1>>>();
    scatter_kernel<<<TK / 256, 256>>>();
    fused_moe_kernel<<<MAX_TILES, 256, SMEM_BYTES>>>(x, wgu, wd, out);
}